// round 1
// baseline (speedup 1.0000x reference)
#include <cuda_runtime.h>
#include <cstdint>

// OctVolSynth: fused LUT-gather + elementwise synth
//   vessels = lut[label] * texture
//   vessels = (vessels == 0) ? 1 : vessels
//   volume  = parenchyma * vessels
//   mask    = (label != 0)
//
// Inputs (metadata order):
//   d_in[0] = vessel_labels  int32  [D*H*W]
//   d_in[1] = parenchyma     float  [D*H*W]
//   d_in[2] = vessel_texture float  [D*H*W]
//   d_in[3] = label_lut      float  [256]
// Output: d_out float — volume in [0,N), mask (0/1) in [N,2N) if out_size >= 2N.

#define N_LABELS 256

__global__ __launch_bounds__(256)
void octvolsynth_kernel(const int4* __restrict__ labels,
                        const float4* __restrict__ par,
                        const float4* __restrict__ tex,
                        const float* __restrict__ lut,
                        float4* __restrict__ out_vol,
                        float4* __restrict__ out_mask,
                        long n4,
                        int write_mask)
{
    __shared__ float slut[N_LABELS];
    // stage LUT (256 floats) into shared
    if (threadIdx.x < N_LABELS) slut[threadIdx.x] = lut[threadIdx.x];
    __syncthreads();

    long i = (long)blockIdx.x * blockDim.x + threadIdx.x;
    if (i >= n4) return;

    int4   lb = labels[i];
    float4 p  = par[i];
    float4 t  = tex[i];

    float v0 = slut[lb.x] * t.x;
    float v1 = slut[lb.y] * t.y;
    float v2 = slut[lb.z] * t.z;
    float v3 = slut[lb.w] * t.w;
    v0 = (v0 == 0.0f) ? 1.0f : v0;
    v1 = (v1 == 0.0f) ? 1.0f : v1;
    v2 = (v2 == 0.0f) ? 1.0f : v2;
    v3 = (v3 == 0.0f) ? 1.0f : v3;

    float4 o;
    o.x = p.x * v0;
    o.y = p.y * v1;
    o.z = p.z * v2;
    o.w = p.w * v3;
    out_vol[i] = o;

    if (write_mask) {
        float4 m;
        m.x = lb.x ? 1.0f : 0.0f;
        m.y = lb.y ? 1.0f : 0.0f;
        m.z = lb.z ? 1.0f : 0.0f;
        m.w = lb.w ? 1.0f : 0.0f;
        out_mask[i] = m;
    }
}

extern "C" void kernel_launch(void* const* d_in, const int* in_sizes, int n_in,
                              void* d_out, int out_size)
{
    const int*   labels = (const int*)d_in[0];
    const float* par    = (const float*)d_in[1];
    const float* tex    = (const float*)d_in[2];
    const float* lut    = (const float*)d_in[3];

    long n  = (long)in_sizes[0];           // 67,108,864
    long n4 = n / 4;                       // exactly divisible (64M % 4 == 0)

    float* out   = (float*)d_out;
    int write_mask = (out_size >= 2 * n) ? 1 : 0;

    int threads = 256;
    long blocks = (n4 + threads - 1) / threads;

    octvolsynth_kernel<<<(unsigned)blocks, threads>>>(
        (const int4*)labels,
        (const float4*)par,
        (const float4*)tex,
        lut,
        (float4*)out,
        (float4*)(out + n),
        n4,
        write_mask);
}